// round 1
// baseline (speedup 1.0000x reference)
#include <cuda_runtime.h>
#include <math.h>

#define NG 512
#define W 320
#define H 240
#define NEARP 0.1f
#define FARP 100.0f
#define NF 14   // floats per packed gaussian

// Packed per-gaussian fields:
// 0:xmin 1:xmax 2:ymin 3:ymax 4:px 5:py 6:ia 7:ib 8:ic 9:op 10:r 11:g 12:b 13:z
__device__ float g_pre[NG * NF];
__device__ float g_sorted[NG * NF];
__device__ int   g_M;

__device__ __forceinline__ bool comes_before(float ka, int ia, float kb, int ib) {
    // descending key, ascending index on ties (matches stable argsort(-key))
    return (ka > kb) || (ka == kb && ia < ib);
}

__global__ void __launch_bounds__(NG)
preprocess_sort_kernel(const float* __restrict__ means,
                       const float* __restrict__ scales,
                       const float* __restrict__ rots,
                       const float* __restrict__ colors,
                       const float* __restrict__ ops,
                       const float* __restrict__ Kc,
                       const float* __restrict__ Tm,
                       float* __restrict__ radii_out) {
    const int i = threadIdx.x;

    const float fx = Kc[0], fy = Kc[4], cxk = Kc[2], cyk = Kc[5];
    const float Rc00 = Tm[0], Rc01 = Tm[1], Rc02 = Tm[2],  t0 = Tm[3];
    const float Rc10 = Tm[4], Rc11 = Tm[5], Rc12 = Tm[6],  t1 = Tm[7];
    const float Rc20 = Tm[8], Rc21 = Tm[9], Rc22 = Tm[10], t2 = Tm[11];

    const float mx = means[i*3+0], my = means[i*3+1], mz = means[i*3+2];
    const float xc = Rc00*mx + Rc01*my + Rc02*mz + t0;
    const float yc = Rc10*mx + Rc11*my + Rc12*mz + t1;
    const float zc = Rc20*mx + Rc21*my + Rc22*mz + t2;
    const float zs = (zc == 0.0f) ? 1e-8f : zc;

    const float iz = 1.0f / zs;
    const float pxv = fx * xc * iz + cxk;
    const float pyv = fy * yc * iz + cyk;

    // quaternion -> rotation
    float qw = rots[i*4+0], qx = rots[i*4+1], qy = rots[i*4+2], qz = rots[i*4+3];
    const float qn = sqrtf(qw*qw + qx*qx + qy*qy + qz*qz);
    qw /= qn; qx /= qn; qy /= qn; qz /= qn;
    const float R00 = 1.0f - 2.0f*(qy*qy + qz*qz), R01 = 2.0f*(qx*qy - qw*qz), R02 = 2.0f*(qx*qz + qw*qy);
    const float R10 = 2.0f*(qx*qy + qw*qz), R11 = 1.0f - 2.0f*(qx*qx + qz*qz), R12 = 2.0f*(qy*qz - qw*qx);
    const float R20 = 2.0f*(qx*qz - qw*qy), R21 = 2.0f*(qy*qz + qw*qx), R22 = 1.0f - 2.0f*(qx*qx + qy*qy);

    const float s0 = scales[i*3+0], s1 = scales[i*3+1], s2 = scales[i*3+2];
    const float S0 = s0*s0, S1 = s1*s1, S2 = s2*s2;

    // cov3d = R diag(S) R^T (symmetric)
    const float C00 = R00*R00*S0 + R01*R01*S1 + R02*R02*S2;
    const float C01 = R00*R10*S0 + R01*R11*S1 + R02*R12*S2;
    const float C02 = R00*R20*S0 + R01*R21*S1 + R02*R22*S2;
    const float C11 = R10*R10*S0 + R11*R11*S1 + R12*R12*S2;
    const float C12 = R10*R20*S0 + R11*R21*S1 + R12*R22*S2;
    const float C22 = R20*R20*S0 + R21*R21*S1 + R22*R22*S2;

    // V = Rc * C * Rc^T
    // tmp = Rc * C
    const float T00 = Rc00*C00 + Rc01*C01 + Rc02*C02;
    const float T01 = Rc00*C01 + Rc01*C11 + Rc02*C12;
    const float T02 = Rc00*C02 + Rc01*C12 + Rc02*C22;
    const float T10 = Rc10*C00 + Rc11*C01 + Rc12*C02;
    const float T11 = Rc10*C01 + Rc11*C11 + Rc12*C12;
    const float T12 = Rc10*C02 + Rc11*C12 + Rc12*C22;
    const float T20 = Rc20*C00 + Rc21*C01 + Rc22*C02;
    const float T21 = Rc20*C01 + Rc21*C11 + Rc22*C12;
    const float T22 = Rc20*C02 + Rc21*C12 + Rc22*C22;
    const float V00 = T00*Rc00 + T01*Rc01 + T02*Rc02;
    const float V01 = T00*Rc10 + T01*Rc11 + T02*Rc12;
    const float V02 = T00*Rc20 + T01*Rc21 + T02*Rc22;
    const float V11 = T10*Rc10 + T11*Rc11 + T12*Rc12;
    const float V12 = T10*Rc20 + T11*Rc21 + T12*Rc22;
    const float V22 = T20*Rc20 + T21*Rc21 + T22*Rc22;

    // J (2x3 jacobian of projection)
    const float iz2 = iz * iz;
    const float J00 = fx * iz,  J02 = -fx * xc * iz2;
    const float J11 = fy * iz,  J12 = -fy * yc * iz2;

    // u0 = V * J0^T ; u1 = V * J1^T  (V symmetric)
    const float u0x = V00*J00 + V02*J02;
    const float u0z = V02*J00 + V22*J02;
    const float u1x = V01*J11 + V02*J12;
    const float u1y = V11*J11 + V12*J12;
    const float u1z = V12*J11 + V22*J12;

    const float a = J00*u0x + J02*u0z;
    const float b = J00*u1x + J02*u1z;
    const float c = J11*u1y + J12*u1z;

    const float lam = 0.5f*(a + c) + sqrtf(fmaxf(0.25f*(a - c)*(a - c) + b*b, 0.0f));
    const float radius = 3.0f * sqrtf(fmaxf(lam, 0.0f));

    const bool visible = (zc > NEARP) && (zc < FARP) &&
                         (pxv >= 0.0f) && (pxv < (float)W) &&
                         (pyv >= 0.0f) && (pyv < (float)H);

    radii_out[i] = visible ? radius : 0.0f;

    // inverse conic with reference eps
    const float ae = a + 1e-6f, ce = c + 1e-6f;
    const float det = ae*ce - b*b;
    const float idet = 1.0f / det;

    const float cxp = floorf(pxv), cyp = floorf(pyv);
    const float r_int = floorf(radius) + 1.0f;

    float* p = &g_pre[i * NF];
    p[0]  = cxp - r_int;
    p[1]  = cxp + r_int;
    p[2]  = cyp - r_int;
    p[3]  = cyp + r_int;
    p[4]  = pxv;
    p[5]  = pyv;
    p[6]  = ce * idet;
    p[7]  = -b * idet;
    p[8]  = ae * idet;
    p[9]  = ops[i];
    p[10] = colors[i*3+0];
    p[11] = colors[i*3+1];
    p[12] = colors[i*3+2];
    p[13] = zc;

    // ---- bitonic sort on (key desc, idx asc) ----
    __shared__ float sk[NG];
    __shared__ int   si[NG];
    __shared__ int   sM;

    sk[i] = visible ? zc : -1e30f;
    si[i] = i;
    if (i == 0) sM = 0;
    __syncthreads();

    for (int k = 2; k <= NG; k <<= 1) {
        for (int j = k >> 1; j > 0; j >>= 1) {
            const int ixj = i ^ j;
            if (ixj > i) {
                const bool asc = ((i & k) == 0);
                const float k1 = sk[i], k2 = sk[ixj];
                const int i1 = si[i], i2 = si[ixj];
                const bool cb = comes_before(k1, i1, k2, i2);
                // sequence should be "comes_before"-ascending in asc segments
                if (cb != asc) {
                    sk[i] = k2; si[i] = i2;
                    sk[ixj] = k1; si[ixj] = i1;
                }
            }
            __syncthreads();
        }
    }

    if (sk[i] > -1e29f) atomicAdd(&sM, 1);
    __syncthreads();

    const int M = sM;
    if (i == 0) g_M = M;
    if (i < M) {
        const int src = si[i];
        const float* s = &g_pre[src * NF];
        float* d = &g_sorted[i * NF];
        #pragma unroll
        for (int f = 0; f < NF; f++) d[f] = s[f];
    }
}

__global__ void __launch_bounds__(256)
rasterize_kernel(float* __restrict__ out) {
    __shared__ float sg[NG * NF];    // 28 KB
    __shared__ int s_warpoff[8];
    __shared__ int s_cnt;

    const int tid = threadIdx.y * 16 + threadIdx.x;
    const int lane = tid & 31, wid = tid >> 5;
    const int tile_x0 = blockIdx.x * 16;
    const int tile_y0 = blockIdx.y * 16;
    const float tx0 = (float)tile_x0, tx1 = (float)(tile_x0 + 15);
    const float ty0 = (float)tile_y0, ty1 = (float)(tile_y0 + 15);

    const int M = g_M;
    if (tid == 0) s_cnt = 0;
    __syncthreads();

    // ordered tile culling: compact gaussians intersecting this tile, preserving order
    for (int base = 0; base < M; base += 256) {
        const int gi = base + tid;
        bool pred = false;
        if (gi < M) {
            const float* g = &g_sorted[gi * NF];
            pred = (g[1] >= tx0) && (g[0] <= tx1) && (g[3] >= ty0) && (g[2] <= ty1);
        }
        const unsigned bal = __ballot_sync(0xffffffffu, pred);
        const int wcount = __popc(bal);
        const int wprefix = __popc(bal & ((1u << lane) - 1u));
        if (lane == 0) s_warpoff[wid] = wcount;
        __syncthreads();
        if (tid == 0) {
            int run = s_cnt;
            #pragma unroll
            for (int w = 0; w < 8; w++) { const int cc = s_warpoff[w]; s_warpoff[w] = run; run += cc; }
            s_cnt = run;
        }
        __syncthreads();
        if (pred) {
            const int dst = s_warpoff[wid] + wprefix;
            const float* g = &g_sorted[gi * NF];
            float* d = &sg[dst * NF];
            #pragma unroll
            for (int f = 0; f < NF; f++) d[f] = g[f];
        }
        __syncthreads();
    }
    const int cnt = s_cnt;

    const float gx = (float)(tile_x0 + threadIdx.x);
    const float gy = (float)(tile_y0 + threadIdx.y);

    float Tr = 1.0f;
    float cr = 0.0f, cg = 0.0f, cb = 0.0f;
    float asum = 0.0f;
    float depth = 0.0f;
    bool hasd = false;

    for (int j = 0; j < cnt; j++) {
        const float* g = &sg[j * NF];
        if (gx < g[0] || gx > g[1] || gy < g[2] || gy > g[3]) continue;
        const float dx = gx - g[4];
        const float dy = gy - g[5];
        const float mah = g[6]*dx*dx + 2.0f*g[7]*dx*dy + g[8]*dy*dy;
        float al = g[9] * expf(-0.5f * mah);
        al = fminf(al, 0.99f);
        const float w = al * Tr;
        cr += w * g[10];
        cg += w * g[11];
        cb += w * g[12];
        asum += w;
        if (!hasd && w > 0.01f) { hasd = true; depth = g[13]; }
        Tr *= (1.0f - al);
        if (Tr < 1e-7f) break;   // residual contributions bounded by Tr; depth already final (Tr<=0.01)
    }

    const int px = tile_x0 + threadIdx.x;
    const int py = tile_y0 + threadIdx.y;
    const int pix = py * W + px;

    out[pix*3 + 0] = fminf(fmaxf(cr, 0.0f), 1.0f);
    out[pix*3 + 1] = fminf(fmaxf(cg, 0.0f), 1.0f);
    out[pix*3 + 2] = fminf(fmaxf(cb, 0.0f), 1.0f);
    out[H*W*3 + pix] = hasd ? depth : 0.0f;                 // depth_map
    out[H*W*4 + pix] = fminf(fmaxf(asum, 0.0f), 1.0f);      // alpha_map
}

extern "C" void kernel_launch(void* const* d_in, const int* in_sizes, int n_in,
                              void* d_out, int out_size) {
    const float* means  = (const float*)d_in[0];
    const float* scales = (const float*)d_in[1];
    const float* rots   = (const float*)d_in[2];
    const float* colors = (const float*)d_in[3];
    const float* ops    = (const float*)d_in[4];
    const float* Kc     = (const float*)d_in[5];
    const float* Tm     = (const float*)d_in[6];
    float* out = (float*)d_out;

    preprocess_sort_kernel<<<1, NG>>>(means, scales, rots, colors, ops, Kc, Tm,
                                      out + (size_t)H * W * 5);
    rasterize_kernel<<<dim3(W/16, H/16), dim3(16, 16)>>>(out);
}

// round 2
// speedup vs baseline: 1.7931x; 1.7931x over previous
#include <cuda_runtime.h>
#include <math.h>

#define NG 512
#define W 320
#define H 240
#define NEARP 0.1f
#define FARP 100.0f
#define NTILES_X 20
#define NTILES_Y 15
#define NBLOCKS 150   // 2 tiles per block -> 300 tiles, 1 wave on 152 SMs

__global__ void __launch_bounds__(256)
fused_gauss_kernel(const float* __restrict__ means,
                   const float* __restrict__ scales,
                   const float* __restrict__ rots,
                   const float* __restrict__ colors,
                   const float* __restrict__ ops,
                   const float* __restrict__ Kc,
                   const float* __restrict__ Tm,
                   float* __restrict__ out) {
    // SoA shared storage for all gaussians (per-block recompute)
    __shared__ float4 sA[NG];   // xmin, xmax, ymin, ymax   (or empty box if invisible)
    __shared__ float4 sB[NG];   // px, py, ha(=-.5*ia), hb(=-ib i.e. -.5*2ib)
    __shared__ float4 sC[NG];   // hc(=-.5*ic), op, z, 0
    __shared__ float4 sD[NG];   // r, g, b, 0
    __shared__ int    lidx[NG];
    __shared__ int    ord[NG];
    __shared__ int    s_warpoff[8];
    __shared__ int    s_cnt;

    const int tid  = threadIdx.x;
    const int lane = tid & 31, wid = tid >> 5;

    const float fx = Kc[0], fy = Kc[4], cxk = Kc[2], cyk = Kc[5];
    const float Rc00 = Tm[0], Rc01 = Tm[1], Rc02 = Tm[2],  t0 = Tm[3];
    const float Rc10 = Tm[4], Rc11 = Tm[5], Rc12 = Tm[6],  t1 = Tm[7];
    const float Rc20 = Tm[8], Rc21 = Tm[9], Rc22 = Tm[10], t2 = Tm[11];

    // ---------------- Phase 1: per-gaussian preprocess (2 per thread) -----------
    #pragma unroll
    for (int g = tid; g < NG; g += 256) {
        const float mx = means[g*3+0], my = means[g*3+1], mz = means[g*3+2];
        const float xc = Rc00*mx + Rc01*my + Rc02*mz + t0;
        const float yc = Rc10*mx + Rc11*my + Rc12*mz + t1;
        const float zc = Rc20*mx + Rc21*my + Rc22*mz + t2;
        const float zs = (zc == 0.0f) ? 1e-8f : zc;
        const float iz = 1.0f / zs;
        const float pxv = fx * xc * iz + cxk;
        const float pyv = fy * yc * iz + cyk;

        float qw = rots[g*4+0], qx = rots[g*4+1], qy = rots[g*4+2], qz = rots[g*4+3];
        const float qn = rsqrtf(qw*qw + qx*qx + qy*qy + qz*qz);
        qw *= qn; qx *= qn; qy *= qn; qz *= qn;
        const float R00 = 1.0f - 2.0f*(qy*qy + qz*qz), R01 = 2.0f*(qx*qy - qw*qz), R02 = 2.0f*(qx*qz + qw*qy);
        const float R10 = 2.0f*(qx*qy + qw*qz), R11 = 1.0f - 2.0f*(qx*qx + qz*qz), R12 = 2.0f*(qy*qz - qw*qx);
        const float R20 = 2.0f*(qx*qz - qw*qy), R21 = 2.0f*(qy*qz + qw*qx), R22 = 1.0f - 2.0f*(qx*qx + qy*qy);

        const float s0 = scales[g*3+0], s1 = scales[g*3+1], s2 = scales[g*3+2];
        const float S0 = s0*s0, S1 = s1*s1, S2 = s2*s2;

        const float C00 = R00*R00*S0 + R01*R01*S1 + R02*R02*S2;
        const float C01 = R00*R10*S0 + R01*R11*S1 + R02*R12*S2;
        const float C02 = R00*R20*S0 + R01*R21*S1 + R02*R22*S2;
        const float C11 = R10*R10*S0 + R11*R11*S1 + R12*R12*S2;
        const float C12 = R10*R20*S0 + R11*R21*S1 + R12*R22*S2;
        const float C22 = R20*R20*S0 + R21*R21*S1 + R22*R22*S2;

        // V = Rc * C * Rc^T
        const float T00 = Rc00*C00 + Rc01*C01 + Rc02*C02;
        const float T01 = Rc00*C01 + Rc01*C11 + Rc02*C12;
        const float T02 = Rc00*C02 + Rc01*C12 + Rc02*C22;
        const float T10 = Rc10*C00 + Rc11*C01 + Rc12*C02;
        const float T11 = Rc10*C01 + Rc11*C11 + Rc12*C12;
        const float T12 = Rc10*C02 + Rc11*C12 + Rc12*C22;
        const float T20 = Rc20*C00 + Rc21*C01 + Rc22*C02;
        const float T21 = Rc20*C01 + Rc21*C11 + Rc22*C12;
        const float T22 = Rc20*C02 + Rc21*C12 + Rc22*C22;
        const float V00 = T00*Rc00 + T01*Rc01 + T02*Rc02;
        const float V01 = T00*Rc10 + T01*Rc11 + T02*Rc12;
        const float V02 = T00*Rc20 + T01*Rc21 + T02*Rc22;
        const float V11 = T10*Rc10 + T11*Rc11 + T12*Rc12;
        const float V12 = T10*Rc20 + T11*Rc21 + T12*Rc22;
        const float V22 = T20*Rc20 + T21*Rc21 + T22*Rc22;

        const float iz2 = iz * iz;
        const float J00 = fx * iz,  J02 = -fx * xc * iz2;
        const float J11 = fy * iz,  J12 = -fy * yc * iz2;

        const float u0x = V00*J00 + V02*J02;
        const float u0z = V02*J00 + V22*J02;
        const float u1x = V01*J11 + V02*J12;
        const float u1y = V11*J11 + V12*J12;
        const float u1z = V12*J11 + V22*J12;

        const float a = J00*u0x + J02*u0z;
        const float b = J00*u1x + J02*u1z;
        const float c = J11*u1y + J12*u1z;

        const float lam = 0.5f*(a + c) + sqrtf(fmaxf(0.25f*(a - c)*(a - c) + b*b, 0.0f));
        const float radius = 3.0f * sqrtf(fmaxf(lam, 0.0f));

        const bool visible = (zc > NEARP) && (zc < FARP) &&
                             (pxv >= 0.0f) && (pxv < (float)W) &&
                             (pyv >= 0.0f) && (pyv < (float)H);

        if (blockIdx.x == 0) out[(size_t)H*W*5 + g] = visible ? radius : 0.0f;

        const float ae = a + 1e-6f, ce = c + 1e-6f;
        const float det = ae*ce - b*b;
        const float idet = 1.0f / det;

        const float cxp = floorf(pxv), cyp = floorf(pyv);
        const float r_int = floorf(radius) + 1.0f;

        if (visible) sA[g] = make_float4(cxp - r_int, cxp + r_int, cyp - r_int, cyp + r_int);
        else         sA[g] = make_float4(1e30f, -1e30f, 1e30f, -1e30f);   // empty box

        // fold -0.5 into conic; fold the 2x into the cross term (exact fp scalings)
        sB[g] = make_float4(pxv, pyv, -0.5f * (ce * idet), (b * idet));   // hb = -0.5*2*(-b/det) = b/det
        sC[g] = make_float4(-0.5f * (ae * idet), ops[g], zc, 0.0f);
        sD[g] = make_float4(colors[g*3+0], colors[g*3+1], colors[g*3+2], 0.0f);
    }
    __syncthreads();

    // ---------------- Phase 2..4: two tiles per block ---------------------------
    for (int sub = 0; sub < 2; sub++) {
        const int t = blockIdx.x * 2 + sub;
        const int tile_x0 = (t % NTILES_X) * 16;
        const int tile_y0 = (t / NTILES_X) * 16;
        const float tx0 = (float)tile_x0, tx1 = (float)(tile_x0 + 15);
        const float ty0 = (float)tile_y0, ty1 = (float)(tile_y0 + 15);

        if (tid == 0) s_cnt = 0;
        __syncthreads();

        // ordered cull/compaction (index order preserved)
        #pragma unroll
        for (int base = 0; base < NG; base += 256) {
            const int gi = base + tid;
            const float4 A = sA[gi];
            const bool pred = (A.y >= tx0) && (A.x <= tx1) && (A.w >= ty0) && (A.z <= ty1);
            const unsigned bal = __ballot_sync(0xffffffffu, pred);
            if (lane == 0) s_warpoff[wid] = __popc(bal);
            __syncthreads();
            if (tid == 0) {
                int run = s_cnt;
                #pragma unroll
                for (int w = 0; w < 8; w++) { const int cc = s_warpoff[w]; s_warpoff[w] = run; run += cc; }
                s_cnt = run;
            }
            __syncthreads();
            if (pred) lidx[s_warpoff[wid] + __popc(bal & ((1u << lane) - 1u))] = gi;
            __syncthreads();
        }
        const int cnt = s_cnt;

        // per-tile rank sort on (z desc, index asc); lidx is index-ascending,
        // so position asc == original-index asc -> stable tie-break matches argsort(-key)
        if (tid < cnt) {
            const int gi = lidx[tid];
            const float zk = sC[gi].z;
            int rank = 0;
            for (int j = 0; j < cnt; j++) {
                const float zj = sC[lidx[j]].z;
                rank += (zj > zk) || (zj == zk && j < tid);
            }
            ord[rank] = gi;
        }
        __syncthreads();

        // composite
        const int px = tile_x0 + (tid & 15);
        const int py = tile_y0 + (tid >> 4);
        const float gx = (float)px, gy = (float)py;

        float Tr = 1.0f, cr = 0.0f, cg = 0.0f, cb = 0.0f, asum = 0.0f, depth = 0.0f;
        bool hasd = false;

        for (int j = 0; j < cnt; j++) {
            const int gi = ord[j];
            const float4 A = sA[gi];
            const float4 B = sB[gi];
            const float4 C = sC[gi];
            const float4 D = sD[gi];
            const bool in = (gx >= A.x) && (gx <= A.y) && (gy >= A.z) && (gy <= A.w);
            const float dx = gx - B.x;
            const float dy = gy - B.y;
            const float e = B.z*dx*dx + B.w*dx*dy + C.x*dy*dy;   // = -0.5*mahal
            float al = fminf(C.y * __expf(e), 0.99f);
            al = in ? al : 0.0f;
            const float w = al * Tr;
            cr += w * D.x;
            cg += w * D.y;
            cb += w * D.z;
            asum += w;
            if (!hasd && w > 0.01f) { hasd = true; depth = C.z; }
            Tr *= (1.0f - al);
            if (Tr < 1e-7f) break;  // residual weight <= Tr; depth final once Tr <= 0.01
        }

        const int pix = py * W + px;
        out[pix*3 + 0] = fminf(fmaxf(cr, 0.0f), 1.0f);
        out[pix*3 + 1] = fminf(fmaxf(cg, 0.0f), 1.0f);
        out[pix*3 + 2] = fminf(fmaxf(cb, 0.0f), 1.0f);
        out[(size_t)H*W*3 + pix] = hasd ? depth : 0.0f;
        out[(size_t)H*W*4 + pix] = fminf(fmaxf(asum, 0.0f), 1.0f);

        __syncthreads();   // protect lidx/ord/s_cnt before next tile's cull
    }
}

extern "C" void kernel_launch(void* const* d_in, const int* in_sizes, int n_in,
                              void* d_out, int out_size) {
    const float* means  = (const float*)d_in[0];
    const float* scales = (const float*)d_in[1];
    const float* rots   = (const float*)d_in[2];
    const float* colors = (const float*)d_in[3];
    const float* ops    = (const float*)d_in[4];
    const float* Kc     = (const float*)d_in[5];
    const float* Tm     = (const float*)d_in[6];
    float* out = (float*)d_out;

    fused_gauss_kernel<<<NBLOCKS, 256>>>(means, scales, rots, colors, ops, Kc, Tm, out);
}

// round 3
// speedup vs baseline: 2.4116x; 1.3449x over previous
#include <cuda_runtime.h>
#include <math.h>

#define NG 512
#define W 320
#define H 240
#define NEARP 0.1f
#define FARP 100.0f
#define NTILES_X 20

__global__ void __launch_bounds__(256)
fused_gauss_kernel(const float* __restrict__ means,
                   const float* __restrict__ scales,
                   const float* __restrict__ rots,
                   const float* __restrict__ colors,
                   const float* __restrict__ ops,
                   const float* __restrict__ Kc,
                   const float* __restrict__ Tm,
                   float* __restrict__ out) {
    __shared__ float4 sA[NG];   // xmin, xmax, ymin, ymax  (empty box if invisible)
    __shared__ float4 sB[NG];   // px, py, ha(=-.5*ia), hb(=+b/det)
    __shared__ float4 sC[NG];   // hc(=-.5*ic), op, z, 0
    __shared__ float4 sD[NG];   // r, g, b, 0
    __shared__ float  zv[NG];
    __shared__ int    lidx[NG];
    __shared__ int    ord[NG];
    __shared__ int    s_off[16];
    __shared__ int    s_cnt;

    const int tid  = threadIdx.x;
    const int lane = tid & 31, wid = tid >> 5;

    const float fx = Kc[0], fy = Kc[4], cxk = Kc[2], cyk = Kc[5];
    const float Rc00 = Tm[0], Rc01 = Tm[1], Rc02 = Tm[2],  t0 = Tm[3];
    const float Rc10 = Tm[4], Rc11 = Tm[5], Rc12 = Tm[6],  t1 = Tm[7];
    const float Rc20 = Tm[8], Rc21 = Tm[9], Rc22 = Tm[10], t2 = Tm[11];

    // ---------------- Phase 1: preprocess (2 gaussians per thread) --------------
    #pragma unroll
    for (int g = tid; g < NG; g += 256) {
        // front-load all global inputs for MLP
        const float mx = means[g*3+0], my = means[g*3+1], mz = means[g*3+2];
        float qw = rots[g*4+0], qx = rots[g*4+1], qy = rots[g*4+2], qz = rots[g*4+3];
        const float s0 = scales[g*3+0], s1 = scales[g*3+1], s2 = scales[g*3+2];
        const float col0 = colors[g*3+0], col1 = colors[g*3+1], col2 = colors[g*3+2];
        const float opv = ops[g];

        const float xc = Rc00*mx + Rc01*my + Rc02*mz + t0;
        const float yc = Rc10*mx + Rc11*my + Rc12*mz + t1;
        const float zc = Rc20*mx + Rc21*my + Rc22*mz + t2;
        const float zs = (zc == 0.0f) ? 1e-8f : zc;
        const float iz = 1.0f / zs;
        const float pxv = fx * xc * iz + cxk;
        const float pyv = fy * yc * iz + cyk;

        const float qn = rsqrtf(qw*qw + qx*qx + qy*qy + qz*qz);
        qw *= qn; qx *= qn; qy *= qn; qz *= qn;
        const float R00 = 1.0f - 2.0f*(qy*qy + qz*qz), R01 = 2.0f*(qx*qy - qw*qz), R02 = 2.0f*(qx*qz + qw*qy);
        const float R10 = 2.0f*(qx*qy + qw*qz), R11 = 1.0f - 2.0f*(qx*qx + qz*qz), R12 = 2.0f*(qy*qz - qw*qx);
        const float R20 = 2.0f*(qx*qz - qw*qy), R21 = 2.0f*(qy*qz + qw*qx), R22 = 1.0f - 2.0f*(qx*qx + qy*qy);

        const float S0 = s0*s0, S1 = s1*s1, S2 = s2*s2;

        const float C00 = R00*R00*S0 + R01*R01*S1 + R02*R02*S2;
        const float C01 = R00*R10*S0 + R01*R11*S1 + R02*R12*S2;
        const float C02 = R00*R20*S0 + R01*R21*S1 + R02*R22*S2;
        const float C11 = R10*R10*S0 + R11*R11*S1 + R12*R12*S2;
        const float C12 = R10*R20*S0 + R11*R21*S1 + R12*R22*S2;
        const float C22 = R20*R20*S0 + R21*R21*S1 + R22*R22*S2;

        const float T00 = Rc00*C00 + Rc01*C01 + Rc02*C02;
        const float T01 = Rc00*C01 + Rc01*C11 + Rc02*C12;
        const float T02 = Rc00*C02 + Rc01*C12 + Rc02*C22;
        const float T10 = Rc10*C00 + Rc11*C01 + Rc12*C02;
        const float T11 = Rc10*C01 + Rc11*C11 + Rc12*C12;
        const float T12 = Rc10*C02 + Rc11*C12 + Rc12*C22;
        const float T20 = Rc20*C00 + Rc21*C01 + Rc22*C02;
        const float T21 = Rc20*C01 + Rc21*C11 + Rc22*C12;
        const float T22 = Rc20*C02 + Rc21*C12 + Rc22*C22;
        const float V00 = T00*Rc00 + T01*Rc01 + T02*Rc02;
        const float V01 = T00*Rc10 + T01*Rc11 + T02*Rc12;
        const float V02 = T00*Rc20 + T01*Rc21 + T02*Rc22;
        const float V11 = T10*Rc10 + T11*Rc11 + T12*Rc12;
        const float V12 = T10*Rc20 + T11*Rc21 + T12*Rc22;
        const float V22 = T20*Rc20 + T21*Rc21 + T22*Rc22;

        const float iz2 = iz * iz;
        const float J00 = fx * iz,  J02 = -fx * xc * iz2;
        const float J11 = fy * iz,  J12 = -fy * yc * iz2;

        const float u0x = V00*J00 + V02*J02;
        const float u0z = V02*J00 + V22*J02;
        const float u1x = V01*J11 + V02*J12;
        const float u1y = V11*J11 + V12*J12;
        const float u1z = V12*J11 + V22*J12;

        const float a = J00*u0x + J02*u0z;
        const float b = J00*u1x + J02*u1z;
        const float c = J11*u1y + J12*u1z;

        const float lam = 0.5f*(a + c) + sqrtf(fmaxf(0.25f*(a - c)*(a - c) + b*b, 0.0f));
        const float radius = 3.0f * sqrtf(fmaxf(lam, 0.0f));

        const bool visible = (zc > NEARP) && (zc < FARP) &&
                             (pxv >= 0.0f) && (pxv < (float)W) &&
                             (pyv >= 0.0f) && (pyv < (float)H);

        if (blockIdx.x == 0) out[(size_t)H*W*5 + g] = visible ? radius : 0.0f;

        const float ae = a + 1e-6f, ce = c + 1e-6f;
        const float det = ae*ce - b*b;
        const float idet = 1.0f / det;

        const float cxp = floorf(pxv), cyp = floorf(pyv);
        const float r_int = floorf(radius) + 1.0f;

        sA[g] = visible ? make_float4(cxp - r_int, cxp + r_int, cyp - r_int, cyp + r_int)
                        : make_float4(1e30f, -1e30f, 1e30f, -1e30f);
        sB[g] = make_float4(pxv, pyv, -0.5f * (ce * idet), (b * idet));
        sC[g] = make_float4(-0.5f * (ae * idet), opv, zc, 0.0f);
        sD[g] = make_float4(col0, col1, col2, 0.0f);
    }
    __syncthreads();

    // ---------------- Phase 2: ordered cull (2 barriers total) ------------------
    const int t = blockIdx.x;
    const int tile_x0 = (t % NTILES_X) * 16;
    const int tile_y0 = (t / NTILES_X) * 16;
    const float tx0 = (float)tile_x0, tx1 = (float)(tile_x0 + 15);
    const float ty0 = (float)tile_y0, ty1 = (float)(tile_y0 + 15);

    const float4 A0 = sA[tid];
    const float4 A1 = sA[tid + 256];
    const bool p0 = (A0.y >= tx0) && (A0.x <= tx1) && (A0.w >= ty0) && (A0.z <= ty1);
    const bool p1 = (A1.y >= tx0) && (A1.x <= tx1) && (A1.w >= ty0) && (A1.z <= ty1);
    const unsigned b0 = __ballot_sync(0xffffffffu, p0);
    const unsigned b1 = __ballot_sync(0xffffffffu, p1);
    if (lane == 0) { s_off[wid] = __popc(b0); s_off[8 + wid] = __popc(b1); }
    __syncthreads();

    if (wid == 0) {
        int v = (lane < 16) ? s_off[lane] : 0;
        int inc = v;
        #pragma unroll
        for (int d = 1; d < 16; d <<= 1) {
            const int n = __shfl_up_sync(0xffffffffu, inc, d);
            if (lane >= d) inc += n;
        }
        if (lane < 16) s_off[lane] = inc - v;          // exclusive prefix
        if (lane == 15) s_cnt = inc;                   // total
    }
    __syncthreads();

    if (p0) {
        const int dst = s_off[wid] + __popc(b0 & ((1u << lane) - 1u));
        lidx[dst] = tid;
        zv[dst] = sC[tid].z;
    }
    if (p1) {
        const int dst = s_off[8 + wid] + __popc(b1 & ((1u << lane) - 1u));
        lidx[dst] = tid + 256;
        zv[dst] = sC[tid + 256].z;
    }
    __syncthreads();
    const int cnt = s_cnt;

    // ---------------- Phase 3: rank sort (z desc, index asc) --------------------
    // lidx is index-ascending, so position asc == original-index asc (stable)
    for (int k = tid; k < cnt; k += 256) {
        const float zk = zv[k];
        int rank = 0;
        for (int j = 0; j < cnt; j++) {
            const float zj = zv[j];
            rank += (zj > zk) || (zj == zk && j < k);
        }
        ord[rank] = lidx[k];
    }
    __syncthreads();

    // ---------------- Phase 4: composite ----------------------------------------
    const int px = tile_x0 + (tid & 15);
    const int py = tile_y0 + (tid >> 4);
    const float gx = (float)px, gy = (float)py;

    float Tr = 1.0f, cr = 0.0f, cg = 0.0f, cb = 0.0f, asum = 0.0f, depth = 0.0f;
    bool hasd = false;

    for (int j = 0; j < cnt; j++) {
        const int gi = ord[j];
        const float4 A = sA[gi];
        const float4 B = sB[gi];
        const float4 C = sC[gi];
        const float4 D = sD[gi];
        const bool in = (gx >= A.x) && (gx <= A.y) && (gy >= A.z) && (gy <= A.w);
        const float dx = gx - B.x;
        const float dy = gy - B.y;
        const float e = B.z*dx*dx + B.w*dx*dy + C.x*dy*dy;   // = -0.5*mahal
        float al = fminf(C.y * __expf(e), 0.99f);
        al = in ? al : 0.0f;
        const float w = al * Tr;
        cr += w * D.x;
        cg += w * D.y;
        cb += w * D.z;
        asum += w;
        if (!hasd && w > 0.01f) { hasd = true; depth = C.z; }
        Tr *= (1.0f - al);
        if (Tr < 1e-7f) break;   // residual weight <= Tr; depth final once Tr <= 0.01
    }

    const int pix = py * W + px;
    out[pix*3 + 0] = fminf(fmaxf(cr, 0.0f), 1.0f);
    out[pix*3 + 1] = fminf(fmaxf(cg, 0.0f), 1.0f);
    out[pix*3 + 2] = fminf(fmaxf(cb, 0.0f), 1.0f);
    out[(size_t)H*W*3 + pix] = hasd ? depth : 0.0f;
    out[(size_t)H*W*4 + pix] = fminf(fmaxf(asum, 0.0f), 1.0f);
}

extern "C" void kernel_launch(void* const* d_in, const int* in_sizes, int n_in,
                              void* d_out, int out_size) {
    const float* means  = (const float*)d_in[0];
    const float* scales = (const float*)d_in[1];
    const float* rots   = (const float*)d_in[2];
    const float* colors = (const float*)d_in[3];
    const float* ops    = (const float*)d_in[4];
    const float* Kc     = (const float*)d_in[5];
    const float* Tm     = (const float*)d_in[6];
    float* out = (float*)d_out;

    fused_gauss_kernel<<<300, 256>>>(means, scales, rots, colors, ops, Kc, Tm, out);
}

// round 4
// speedup vs baseline: 2.4186x; 1.0029x over previous
#include <cuda_runtime.h>
#include <math.h>

#define NG 512
#define W 320
#define H 240
#define NEARP 0.1f
#define FARP 100.0f
#define NTILES_X 20
#define NL2E 1.44269504088896f   // log2(e)

__device__ __forceinline__ float ex2(float x) {
    float r;
    asm("ex2.approx.ftz.f32 %0, %1;" : "=f"(r) : "f"(x));
    return r;
}

__global__ void __launch_bounds__(256)
fused_gauss_kernel(const float* __restrict__ means,
                   const float* __restrict__ scales,
                   const float* __restrict__ rots,
                   const float* __restrict__ colors,
                   const float* __restrict__ ops,
                   const float* __restrict__ Kc,
                   const float* __restrict__ Tm,
                   float* __restrict__ out) {
    __shared__ float4 sP[NG];   // cxp, cyp, r_int, fpx   (r_int=-1e30 if invisible)
    __shared__ float4 sQ[NG];   // fpy, ha, hb, hc        (conic * -0.5*log2e)
    __shared__ float4 sR[NG];   // op, r, g, b
    __shared__ float  sZ[NG];   // z
    __shared__ float  zv[NG];
    __shared__ int    lidx[NG];
    __shared__ int    ord[NG];
    __shared__ int    s_off[16];
    __shared__ int    s_cnt;

    const int tid  = threadIdx.x;
    const int lane = tid & 31, wid = tid >> 5;

    const float fx = Kc[0], fy = Kc[4], cxk = Kc[2], cyk = Kc[5];
    const float Rc00 = Tm[0], Rc01 = Tm[1], Rc02 = Tm[2],  t0 = Tm[3];
    const float Rc10 = Tm[4], Rc11 = Tm[5], Rc12 = Tm[6],  t1 = Tm[7];
    const float Rc20 = Tm[8], Rc21 = Tm[9], Rc22 = Tm[10], t2 = Tm[11];

    // ---------------- Phase 1: preprocess (2 gaussians per thread) --------------
    #pragma unroll
    for (int g = tid; g < NG; g += 256) {
        const float mx = means[g*3+0], my = means[g*3+1], mz = means[g*3+2];
        float qw = rots[g*4+0], qx = rots[g*4+1], qy = rots[g*4+2], qz = rots[g*4+3];
        const float s0 = scales[g*3+0], s1 = scales[g*3+1], s2 = scales[g*3+2];
        const float col0 = colors[g*3+0], col1 = colors[g*3+1], col2 = colors[g*3+2];
        const float opv = ops[g];

        const float xc = Rc00*mx + Rc01*my + Rc02*mz + t0;
        const float yc = Rc10*mx + Rc11*my + Rc12*mz + t1;
        const float zc = Rc20*mx + Rc21*my + Rc22*mz + t2;
        const float zs = (zc == 0.0f) ? 1e-8f : zc;
        const float iz = 1.0f / zs;
        const float pxv = fx * xc * iz + cxk;
        const float pyv = fy * yc * iz + cyk;

        const float qn = rsqrtf(qw*qw + qx*qx + qy*qy + qz*qz);
        qw *= qn; qx *= qn; qy *= qn; qz *= qn;
        const float R00 = 1.0f - 2.0f*(qy*qy + qz*qz), R01 = 2.0f*(qx*qy - qw*qz), R02 = 2.0f*(qx*qz + qw*qy);
        const float R10 = 2.0f*(qx*qy + qw*qz), R11 = 1.0f - 2.0f*(qx*qx + qz*qz), R12 = 2.0f*(qy*qz - qw*qx);
        const float R20 = 2.0f*(qx*qz - qw*qy), R21 = 2.0f*(qy*qz + qw*qx), R22 = 1.0f - 2.0f*(qx*qx + qy*qy);

        const float S0 = s0*s0, S1 = s1*s1, S2 = s2*s2;

        const float C00 = R00*R00*S0 + R01*R01*S1 + R02*R02*S2;
        const float C01 = R00*R10*S0 + R01*R11*S1 + R02*R12*S2;
        const float C02 = R00*R20*S0 + R01*R21*S1 + R02*R22*S2;
        const float C11 = R10*R10*S0 + R11*R11*S1 + R12*R12*S2;
        const float C12 = R10*R20*S0 + R11*R21*S1 + R12*R22*S2;
        const float C22 = R20*R20*S0 + R21*R21*S1 + R22*R22*S2;

        const float T00 = Rc00*C00 + Rc01*C01 + Rc02*C02;
        const float T01 = Rc00*C01 + Rc01*C11 + Rc02*C12;
        const float T02 = Rc00*C02 + Rc01*C12 + Rc02*C22;
        const float T10 = Rc10*C00 + Rc11*C01 + Rc12*C02;
        const float T11 = Rc10*C01 + Rc11*C11 + Rc12*C12;
        const float T12 = Rc10*C02 + Rc11*C12 + Rc12*C22;
        const float T20 = Rc20*C00 + Rc21*C01 + Rc22*C02;
        const float T21 = Rc20*C01 + Rc21*C11 + Rc22*C12;
        const float T22 = Rc20*C02 + Rc21*C12 + Rc22*C22;
        const float V00 = T00*Rc00 + T01*Rc01 + T02*Rc02;
        const float V01 = T00*Rc10 + T01*Rc11 + T02*Rc12;
        const float V02 = T00*Rc20 + T01*Rc21 + T02*Rc22;
        const float V11 = T10*Rc10 + T11*Rc11 + T12*Rc12;
        const float V12 = T10*Rc20 + T11*Rc21 + T12*Rc22;
        const float V22 = T20*Rc20 + T21*Rc21 + T22*Rc22;

        const float iz2 = iz * iz;
        const float J00 = fx * iz,  J02 = -fx * xc * iz2;
        const float J11 = fy * iz,  J12 = -fy * yc * iz2;

        const float u0x = V00*J00 + V02*J02;
        const float u0z = V02*J00 + V22*J02;
        const float u1x = V01*J11 + V02*J12;
        const float u1y = V11*J11 + V12*J12;
        const float u1z = V12*J11 + V22*J12;

        const float a = J00*u0x + J02*u0z;
        const float b = J00*u1x + J02*u1z;
        const float c = J11*u1y + J12*u1z;

        const float lam = 0.5f*(a + c) + sqrtf(fmaxf(0.25f*(a - c)*(a - c) + b*b, 0.0f));
        const float radius = 3.0f * sqrtf(fmaxf(lam, 0.0f));

        const bool visible = (zc > NEARP) && (zc < FARP) &&
                             (pxv >= 0.0f) && (pxv < (float)W) &&
                             (pyv >= 0.0f) && (pyv < (float)H);

        if (blockIdx.x == 0) out[(size_t)H*W*5 + g] = visible ? radius : 0.0f;

        const float ae = a + 1e-6f, ce = c + 1e-6f;
        const float det = ae*ce - b*b;
        const float idet = 1.0f / det;

        const float cxp = floorf(pxv), cyp = floorf(pyv);
        const float r_int = visible ? (floorf(radius) + 1.0f) : -1e30f;

        sP[g] = make_float4(cxp, cyp, r_int, pxv - cxp);
        sQ[g] = make_float4(pyv - cyp,
                            -0.5f * NL2E * (ce * idet),
                             NL2E * (b * idet),
                            -0.5f * NL2E * (ae * idet));
        sR[g] = make_float4(opv, col0, col1, col2);
        sZ[g] = zc;
    }
    __syncthreads();

    // ---------------- Phase 2: ordered cull -------------------------------------
    const int t = blockIdx.x;
    const int tile_x0 = (t % NTILES_X) * 16;
    const int tile_y0 = (t / NTILES_X) * 16;
    const float tx0 = (float)tile_x0, tx1 = (float)(tile_x0 + 15);
    const float ty0 = (float)tile_y0, ty1 = (float)(tile_y0 + 15);

    const float4 P0 = sP[tid];
    const float4 P1 = sP[tid + 256];
    const bool p0 = (P0.x - P0.z <= tx1) && (P0.x + P0.z >= tx0) &&
                    (P0.y - P0.z <= ty1) && (P0.y + P0.z >= ty0);
    const bool p1 = (P1.x - P1.z <= tx1) && (P1.x + P1.z >= tx0) &&
                    (P1.y - P1.z <= ty1) && (P1.y + P1.z >= ty0);
    const unsigned b0 = __ballot_sync(0xffffffffu, p0);
    const unsigned b1 = __ballot_sync(0xffffffffu, p1);
    if (lane == 0) { s_off[wid] = __popc(b0); s_off[8 + wid] = __popc(b1); }
    __syncthreads();

    if (wid == 0) {
        int v = (lane < 16) ? s_off[lane] : 0;
        int inc = v;
        #pragma unroll
        for (int d = 1; d < 16; d <<= 1) {
            const int n = __shfl_up_sync(0xffffffffu, inc, d);
            if (lane >= d) inc += n;
        }
        if (lane < 16) s_off[lane] = inc - v;
        if (lane == 15) s_cnt = inc;
    }
    __syncthreads();

    if (p0) {
        const int dst = s_off[wid] + __popc(b0 & ((1u << lane) - 1u));
        lidx[dst] = tid;  zv[dst] = sZ[tid];
    }
    if (p1) {
        const int dst = s_off[8 + wid] + __popc(b1 & ((1u << lane) - 1u));
        lidx[dst] = tid + 256;  zv[dst] = sZ[tid + 256];
    }
    __syncthreads();
    const int cnt = s_cnt;

    // ---------------- Phase 3: rank sort (z desc, index asc) --------------------
    for (int k = tid; k < cnt; k += 256) {
        const float zk = zv[k];
        int rank = 0;
        for (int j = 0; j < cnt; j++) {
            const float zj = zv[j];
            rank += (zj > zk) || (zj == zk && j < k);
        }
        ord[rank] = lidx[k];
    }
    __syncthreads();

    // ---------------- Phase 4: composite ----------------------------------------
    const int px = tile_x0 + (tid & 15);
    const int py = tile_y0 + (tid >> 4);
    const float gx = (float)px, gy = (float)py;

    float Tr = 1.0f, cr = 0.0f, cg = 0.0f, cb = 0.0f, asum = 0.0f;
    int jhit = -1;

    #define BODY(JJ) {                                                        \
        const int gi = ord[JJ];                                               \
        const float4 P = sP[gi];                                              \
        const bool in = (fabsf(gx - P.x) <= P.z) && (fabsf(gy - P.y) <= P.z); \
        if (__any_sync(0xffffffffu, in)) {                                    \
            const float4 Q = sQ[gi];                                          \
            const float4 R = sR[gi];                                          \
            const float dx = (gx - P.x) - P.w;                                \
            const float dy = (gy - P.y) - Q.x;                                \
            const float e  = dx*(Q.y*dx + Q.z*dy) + (Q.w*dy)*dy;              \
            float al = fminf(R.x * ex2(e), 0.99f);                            \
            al = in ? al : 0.0f;                                              \
            const float w = al * Tr;                                          \
            cr += w * R.y; cg += w * R.z; cb += w * R.w; asum += w;           \
            jhit = (jhit < 0 && w > 0.01f) ? (JJ) : jhit;                     \
            Tr = Tr - al * Tr;                                                \
        }                                                                     \
    }

    const int cnt4 = cnt & ~3;
    bool done = false;
    for (int j = 0; j < cnt4; j += 4) {
        BODY(j); BODY(j+1); BODY(j+2); BODY(j+3);
        if (__all_sync(0xffffffffu, Tr < 1e-7f)) { done = true; break; }
    }
    if (!done) {
        for (int j = cnt4; j < cnt; j++) BODY(j);
    }
    #undef BODY

    float depth = 0.0f;
    if (jhit >= 0) depth = sZ[ord[jhit]];

    const int pix = py * W + px;
    out[pix*3 + 0] = fminf(fmaxf(cr, 0.0f), 1.0f);
    out[pix*3 + 1] = fminf(fmaxf(cg, 0.0f), 1.0f);
    out[pix*3 + 2] = fminf(fmaxf(cb, 0.0f), 1.0f);
    out[(size_t)H*W*3 + pix] = depth;
    out[(size_t)H*W*4 + pix] = fminf(fmaxf(asum, 0.0f), 1.0f);
}

extern "C" void kernel_launch(void* const* d_in, const int* in_sizes, int n_in,
                              void* d_out, int out_size) {
    const float* means  = (const float*)d_in[0];
    const float* scales = (const float*)d_in[1];
    const float* rots   = (const float*)d_in[2];
    const float* colors = (const float*)d_in[3];
    const float* ops    = (const float*)d_in[4];
    const float* Kc     = (const float*)d_in[5];
    const float* Tm     = (const float*)d_in[6];
    float* out = (float*)d_out;

    fused_gauss_kernel<<<300, 256>>>(means, scales, rots, colors, ops, Kc, Tm, out);
}

// round 5
// speedup vs baseline: 2.4688x; 1.0208x over previous
#include <cuda_runtime.h>
#include <math.h>

#define NG 512
#define W 320
#define H 240
#define NEARP 0.1f
#define FARP 100.0f
#define NTILES_X 20
#define NL2E 1.44269504088896f   // log2(e)

__device__ __forceinline__ float ex2(float x) {
    float r;
    asm("ex2.approx.ftz.f32 %0, %1;" : "=f"(r) : "f"(x));
    return r;
}

__global__ void __launch_bounds__(512)
fused_gauss_kernel(const float* __restrict__ means,
                   const float* __restrict__ scales,
                   const float* __restrict__ rots,
                   const float* __restrict__ colors,
                   const float* __restrict__ ops,
                   const float* __restrict__ Kc,
                   const float* __restrict__ Tm,
                   float* __restrict__ out) {
    __shared__ float4 sP[NG];     // cxp, cyp, r_int, fpx   (r_int=-1e30 if invisible)
    __shared__ float4 sQ[NG];     // fpy, ha, hb, hc        (conic * -0.5*log2e folded)
    __shared__ float4 sR[NG];     // op, r, g, b
    __shared__ float  sZ[NG];     // z
    __shared__ float  zvA[NG], zvB[NG];
    __shared__ int    lidxA[NG], lidxB[NG];
    __shared__ int    ordA[NG],  ordB[NG];
    __shared__ int    s_offA[16], s_offB[16];
    __shared__ int    s_cntA, s_cntB;

    const int tid  = threadIdx.x;
    const int lane = tid & 31, wid = tid >> 5;

    const float fx = Kc[0], fy = Kc[4], cxk = Kc[2], cyk = Kc[5];
    const float Rc00 = Tm[0], Rc01 = Tm[1], Rc02 = Tm[2],  t0 = Tm[3];
    const float Rc10 = Tm[4], Rc11 = Tm[5], Rc12 = Tm[6],  t1 = Tm[7];
    const float Rc20 = Tm[8], Rc21 = Tm[9], Rc22 = Tm[10], t2 = Tm[11];

    // ---------------- Phase 1: preprocess — exactly 1 gaussian per thread -------
    {
        const int g = tid;
        const float mx = means[g*3+0], my = means[g*3+1], mz = means[g*3+2];
        float qw = rots[g*4+0], qx = rots[g*4+1], qy = rots[g*4+2], qz = rots[g*4+3];
        const float s0 = scales[g*3+0], s1 = scales[g*3+1], s2 = scales[g*3+2];
        const float col0 = colors[g*3+0], col1 = colors[g*3+1], col2 = colors[g*3+2];
        const float opv = ops[g];

        const float xc = Rc00*mx + Rc01*my + Rc02*mz + t0;
        const float yc = Rc10*mx + Rc11*my + Rc12*mz + t1;
        const float zc = Rc20*mx + Rc21*my + Rc22*mz + t2;
        const float zs = (zc == 0.0f) ? 1e-8f : zc;
        const float iz = 1.0f / zs;
        const float pxv = fx * xc * iz + cxk;
        const float pyv = fy * yc * iz + cyk;

        const float qn = rsqrtf(qw*qw + qx*qx + qy*qy + qz*qz);
        qw *= qn; qx *= qn; qy *= qn; qz *= qn;
        const float R00 = 1.0f - 2.0f*(qy*qy + qz*qz), R01 = 2.0f*(qx*qy - qw*qz), R02 = 2.0f*(qx*qz + qw*qy);
        const float R10 = 2.0f*(qx*qy + qw*qz), R11 = 1.0f - 2.0f*(qx*qx + qz*qz), R12 = 2.0f*(qy*qz - qw*qx);
        const float R20 = 2.0f*(qx*qz - qw*qy), R21 = 2.0f*(qy*qz + qw*qx), R22 = 1.0f - 2.0f*(qx*qx + qy*qy);

        const float S0 = s0*s0, S1 = s1*s1, S2 = s2*s2;

        const float C00 = R00*R00*S0 + R01*R01*S1 + R02*R02*S2;
        const float C01 = R00*R10*S0 + R01*R11*S1 + R02*R12*S2;
        const float C02 = R00*R20*S0 + R01*R21*S1 + R02*R22*S2;
        const float C11 = R10*R10*S0 + R11*R11*S1 + R12*R12*S2;
        const float C12 = R10*R20*S0 + R11*R21*S1 + R12*R22*S2;
        const float C22 = R20*R20*S0 + R21*R21*S1 + R22*R22*S2;

        const float T00 = Rc00*C00 + Rc01*C01 + Rc02*C02;
        const float T01 = Rc00*C01 + Rc01*C11 + Rc02*C12;
        const float T02 = Rc00*C02 + Rc01*C12 + Rc02*C22;
        const float T10 = Rc10*C00 + Rc11*C01 + Rc12*C02;
        const float T11 = Rc10*C01 + Rc11*C11 + Rc12*C12;
        const float T12 = Rc10*C02 + Rc11*C12 + Rc12*C22;
        const float T20 = Rc20*C00 + Rc21*C01 + Rc22*C02;
        const float T21 = Rc20*C01 + Rc21*C11 + Rc22*C12;
        const float T22 = Rc20*C02 + Rc21*C12 + Rc22*C22;
        const float V00 = T00*Rc00 + T01*Rc01 + T02*Rc02;
        const float V01 = T00*Rc10 + T01*Rc11 + T02*Rc12;
        const float V02 = T00*Rc20 + T01*Rc21 + T02*Rc22;
        const float V11 = T10*Rc10 + T11*Rc11 + T12*Rc12;
        const float V12 = T10*Rc20 + T11*Rc21 + T12*Rc22;
        const float V22 = T20*Rc20 + T21*Rc21 + T22*Rc22;

        const float iz2 = iz * iz;
        const float J00 = fx * iz,  J02 = -fx * xc * iz2;
        const float J11 = fy * iz,  J12 = -fy * yc * iz2;

        const float u0x = V00*J00 + V02*J02;
        const float u0z = V02*J00 + V22*J02;
        const float u1x = V01*J11 + V02*J12;
        const float u1y = V11*J11 + V12*J12;
        const float u1z = V12*J11 + V22*J12;

        const float a = J00*u0x + J02*u0z;
        const float b = J00*u1x + J02*u1z;
        const float c = J11*u1y + J12*u1z;

        const float lam = 0.5f*(a + c) + sqrtf(fmaxf(0.25f*(a - c)*(a - c) + b*b, 0.0f));
        const float radius = 3.0f * sqrtf(fmaxf(lam, 0.0f));

        const bool visible = (zc > NEARP) && (zc < FARP) &&
                             (pxv >= 0.0f) && (pxv < (float)W) &&
                             (pyv >= 0.0f) && (pyv < (float)H);

        if (blockIdx.x == 0) out[(size_t)H*W*5 + g] = visible ? radius : 0.0f;

        const float ae = a + 1e-6f, ce = c + 1e-6f;
        const float det = ae*ce - b*b;
        const float idet = 1.0f / det;

        const float cxp = floorf(pxv), cyp = floorf(pyv);
        const float r_int = visible ? (floorf(radius) + 1.0f) : -1e30f;

        sP[g] = make_float4(cxp, cyp, r_int, pxv - cxp);
        sQ[g] = make_float4(pyv - cyp,
                            -0.5f * NL2E * (ce * idet),
                             NL2E * (b * idet),
                            -0.5f * NL2E * (ae * idet));
        sR[g] = make_float4(opv, col0, col1, col2);
        sZ[g] = zc;
    }
    __syncthreads();

    // ---------------- Phase 2: dual ordered cull (tiles 2b and 2b+1) ------------
    const int tA = blockIdx.x * 2;
    const int tB = tA + 1;
    const int ax0 = (tA % NTILES_X) * 16, ay0 = (tA / NTILES_X) * 16;
    const int bx0 = (tB % NTILES_X) * 16, by0 = (tB / NTILES_X) * 16;

    {
        const float4 P = sP[tid];
        const bool pA = (P.x - P.z <= (float)(ax0+15)) && (P.x + P.z >= (float)ax0) &&
                        (P.y - P.z <= (float)(ay0+15)) && (P.y + P.z >= (float)ay0);
        const bool pB = (P.x - P.z <= (float)(bx0+15)) && (P.x + P.z >= (float)bx0) &&
                        (P.y - P.z <= (float)(by0+15)) && (P.y + P.z >= (float)by0);
        const unsigned balA = __ballot_sync(0xffffffffu, pA);
        const unsigned balB = __ballot_sync(0xffffffffu, pB);
        if (lane == 0) { s_offA[wid] = __popc(balA); s_offB[wid] = __popc(balB); }
        __syncthreads();

        if (wid == 0) {
            // lanes 0-15 scan A counts, lanes 16-31 scan B counts (independent halves)
            const bool isB = lane >= 16;
            const int l = lane & 15;
            int v = isB ? s_offB[l] : s_offA[l];
            int inc = v;
            #pragma unroll
            for (int d = 1; d < 16; d <<= 1) {
                const int n = __shfl_up_sync(0xffffffffu, inc, d);
                if ((lane & 15) >= d) inc += n;
            }
            if (isB) s_offB[l] = inc - v; else s_offA[l] = inc - v;
            if (l == 15) { if (isB) s_cntB = inc; else s_cntA = inc; }
        }
        __syncthreads();

        if (pA) {
            const int dst = s_offA[wid] + __popc(balA & ((1u << lane) - 1u));
            lidxA[dst] = tid;  zvA[dst] = sZ[tid];
        }
        if (pB) {
            const int dst = s_offB[wid] + __popc(balB & ((1u << lane) - 1u));
            lidxB[dst] = tid;  zvB[dst] = sZ[tid];
        }
        __syncthreads();
    }
    const int cntA = s_cntA;
    const int cntB = s_cntB;

    // ---------------- Phase 3: rank sorts (z desc, index asc) -------------------
    for (int k = tid; k < cntA; k += 512) {
        const float zk = zvA[k];
        int rank = 0;
        for (int j = 0; j < cntA; j++) {
            const float zj = zvA[j];
            rank += (zj > zk) || (zj == zk && j < k);
        }
        ordA[rank] = lidxA[k];
    }
    for (int k = tid; k < cntB; k += 512) {
        const float zk = zvB[k];
        int rank = 0;
        for (int j = 0; j < cntB; j++) {
            const float zj = zvB[j];
            rank += (zj > zk) || (zj == zk && j < k);
        }
        ordB[rank] = lidxB[k];
    }
    __syncthreads();

    // ---------------- Phase 4: composite (warps 0-7 tile A, 8-15 tile B) --------
    const int grp = tid >> 8;          // 0 -> A, 1 -> B
    const int lt  = tid & 255;
    const int* __restrict__ ord = grp ? ordB : ordA;
    const int cnt = grp ? cntB : cntA;
    const int tile_x0 = grp ? bx0 : ax0;
    const int tile_y0 = grp ? by0 : ay0;

    const int px = tile_x0 + (lt & 15);
    const int py = tile_y0 + (lt >> 4);
    const float gx = (float)px, gy = (float)py;

    float Tr = 1.0f, cr = 0.0f, cg = 0.0f, cb = 0.0f, asum = 0.0f;
    int jhit = -1;

    #define BODY(JJ) {                                                        \
        const int gi = ord[JJ];                                               \
        const float4 P = sP[gi];                                              \
        const bool in = (fabsf(gx - P.x) <= P.z) && (fabsf(gy - P.y) <= P.z); \
        if (__any_sync(0xffffffffu, in)) {                                    \
            const float4 Q = sQ[gi];                                          \
            const float4 R = sR[gi];                                          \
            const float dx = (gx - P.x) - P.w;                                \
            const float dy = (gy - P.y) - Q.x;                                \
            const float e  = dx*(Q.y*dx + Q.z*dy) + (Q.w*dy)*dy;              \
            float al = fminf(R.x * ex2(e), 0.99f);                            \
            al = in ? al : 0.0f;                                              \
            const float w = al * Tr;                                          \
            cr += w * R.y; cg += w * R.z; cb += w * R.w; asum += w;           \
            jhit = (jhit < 0 && w > 0.01f) ? (JJ) : jhit;                     \
            Tr = Tr - al * Tr;                                                \
        }                                                                     \
    }

    const int cnt4 = cnt & ~3;
    bool done = false;
    for (int j = 0; j < cnt4; j += 4) {
        BODY(j); BODY(j+1); BODY(j+2); BODY(j+3);
        if (__all_sync(0xffffffffu, Tr < 1e-7f)) { done = true; break; }
    }
    if (!done) {
        for (int j = cnt4; j < cnt; j++) BODY(j);
    }
    #undef BODY

    float depth = 0.0f;
    if (jhit >= 0) depth = sZ[ord[jhit]];

    const int pix = py * W + px;
    out[pix*3 + 0] = fminf(fmaxf(cr, 0.0f), 1.0f);
    out[pix*3 + 1] = fminf(fmaxf(cg, 0.0f), 1.0f);
    out[pix*3 + 2] = fminf(fmaxf(cb, 0.0f), 1.0f);
    out[(size_t)H*W*3 + pix] = depth;
    out[(size_t)H*W*4 + pix] = fminf(fmaxf(asum, 0.0f), 1.0f);
}

extern "C" void kernel_launch(void* const* d_in, const int* in_sizes, int n_in,
                              void* d_out, int out_size) {
    const float* means  = (const float*)d_in[0];
    const float* scales = (const float*)d_in[1];
    const float* rots   = (const float*)d_in[2];
    const float* colors = (const float*)d_in[3];
    const float* ops    = (const float*)d_in[4];
    const float* Kc     = (const float*)d_in[5];
    const float* Tm     = (const float*)d_in[6];
    float* out = (float*)d_out;

    fused_gauss_kernel<<<150, 512>>>(means, scales, rots, colors, ops, Kc, Tm, out);
}

// round 6
// speedup vs baseline: 2.4762x; 1.0030x over previous
#include <cuda_runtime.h>
#include <math.h>

#define NG 512
#define W 320
#define H 240
#define NEARP 0.1f
#define FARP 100.0f
#define NTILES_X 20
#define NL2E 1.44269504088896f   // log2(e)

__device__ float4 g_P[NG];   // cxp, cyp, r_int, fpx   (r_int=-1e30 if invisible)
__device__ float4 g_Q[NG];   // fpy, ha, hb, hc        (conic * -0.5*log2e folded)
__device__ float4 g_R[NG];   // op, r, g, b
__device__ float  g_Z[NG];   // z

__device__ __forceinline__ float ex2(float x) {
    float r;
    asm("ex2.approx.ftz.f32 %0, %1;" : "=f"(r) : "f"(x));
    return r;
}

__global__ void __launch_bounds__(128)
preprocess_kernel(const float* __restrict__ means,
                  const float* __restrict__ scales,
                  const float* __restrict__ rots,
                  const float* __restrict__ colors,
                  const float* __restrict__ ops,
                  const float* __restrict__ Kc,
                  const float* __restrict__ Tm,
                  float* __restrict__ radii_out) {
    const int g = blockIdx.x * 128 + threadIdx.x;

    const float fx = Kc[0], fy = Kc[4], cxk = Kc[2], cyk = Kc[5];
    const float Rc00 = Tm[0], Rc01 = Tm[1], Rc02 = Tm[2],  t0 = Tm[3];
    const float Rc10 = Tm[4], Rc11 = Tm[5], Rc12 = Tm[6],  t1 = Tm[7];
    const float Rc20 = Tm[8], Rc21 = Tm[9], Rc22 = Tm[10], t2 = Tm[11];

    const float mx = means[g*3+0], my = means[g*3+1], mz = means[g*3+2];
    float qw = rots[g*4+0], qx = rots[g*4+1], qy = rots[g*4+2], qz = rots[g*4+3];
    const float s0 = scales[g*3+0], s1 = scales[g*3+1], s2 = scales[g*3+2];
    const float col0 = colors[g*3+0], col1 = colors[g*3+1], col2 = colors[g*3+2];
    const float opv = ops[g];

    const float xc = Rc00*mx + Rc01*my + Rc02*mz + t0;
    const float yc = Rc10*mx + Rc11*my + Rc12*mz + t1;
    const float zc = Rc20*mx + Rc21*my + Rc22*mz + t2;
    const float zs = (zc == 0.0f) ? 1e-8f : zc;
    const float iz = 1.0f / zs;
    const float pxv = fx * xc * iz + cxk;
    const float pyv = fy * yc * iz + cyk;

    const float qn = rsqrtf(qw*qw + qx*qx + qy*qy + qz*qz);
    qw *= qn; qx *= qn; qy *= qn; qz *= qn;
    const float R00 = 1.0f - 2.0f*(qy*qy + qz*qz), R01 = 2.0f*(qx*qy - qw*qz), R02 = 2.0f*(qx*qz + qw*qy);
    const float R10 = 2.0f*(qx*qy + qw*qz), R11 = 1.0f - 2.0f*(qx*qx + qz*qz), R12 = 2.0f*(qy*qz - qw*qx);
    const float R20 = 2.0f*(qx*qz - qw*qy), R21 = 2.0f*(qy*qz + qw*qx), R22 = 1.0f - 2.0f*(qx*qx + qy*qy);

    const float S0 = s0*s0, S1 = s1*s1, S2 = s2*s2;

    const float C00 = R00*R00*S0 + R01*R01*S1 + R02*R02*S2;
    const float C01 = R00*R10*S0 + R01*R11*S1 + R02*R12*S2;
    const float C02 = R00*R20*S0 + R01*R21*S1 + R02*R22*S2;
    const float C11 = R10*R10*S0 + R11*R11*S1 + R12*R12*S2;
    const float C12 = R10*R20*S0 + R11*R21*S1 + R12*R22*S2;
    const float C22 = R20*R20*S0 + R21*R21*S1 + R22*R22*S2;

    const float T00 = Rc00*C00 + Rc01*C01 + Rc02*C02;
    const float T01 = Rc00*C01 + Rc01*C11 + Rc02*C12;
    const float T02 = Rc00*C02 + Rc01*C12 + Rc02*C22;
    const float T10 = Rc10*C00 + Rc11*C01 + Rc12*C02;
    const float T11 = Rc10*C01 + Rc11*C11 + Rc12*C12;
    const float T12 = Rc10*C02 + Rc11*C12 + Rc12*C22;
    const float T20 = Rc20*C00 + Rc21*C01 + Rc22*C02;
    const float T21 = Rc20*C01 + Rc21*C11 + Rc22*C12;
    const float T22 = Rc20*C02 + Rc21*C12 + Rc22*C22;
    const float V00 = T00*Rc00 + T01*Rc01 + T02*Rc02;
    const float V01 = T00*Rc10 + T01*Rc11 + T02*Rc12;
    const float V02 = T00*Rc20 + T01*Rc21 + T02*Rc22;
    const float V11 = T10*Rc10 + T11*Rc11 + T12*Rc12;
    const float V12 = T10*Rc20 + T11*Rc21 + T12*Rc22;
    const float V22 = T20*Rc20 + T21*Rc21 + T22*Rc22;

    const float iz2 = iz * iz;
    const float J00 = fx * iz,  J02 = -fx * xc * iz2;
    const float J11 = fy * iz,  J12 = -fy * yc * iz2;

    const float u0x = V00*J00 + V02*J02;
    const float u0z = V02*J00 + V22*J02;
    const float u1x = V01*J11 + V02*J12;
    const float u1y = V11*J11 + V12*J12;
    const float u1z = V12*J11 + V22*J12;

    const float a = J00*u0x + J02*u0z;
    const float b = J00*u1x + J02*u1z;
    const float c = J11*u1y + J12*u1z;

    const float lam = 0.5f*(a + c) + sqrtf(fmaxf(0.25f*(a - c)*(a - c) + b*b, 0.0f));
    const float radius = 3.0f * sqrtf(fmaxf(lam, 0.0f));

    const bool visible = (zc > NEARP) && (zc < FARP) &&
                         (pxv >= 0.0f) && (pxv < (float)W) &&
                         (pyv >= 0.0f) && (pyv < (float)H);

    radii_out[g] = visible ? radius : 0.0f;

    const float ae = a + 1e-6f, ce = c + 1e-6f;
    const float det = ae*ce - b*b;
    const float idet = 1.0f / det;

    const float cxp = floorf(pxv), cyp = floorf(pyv);
    const float r_int = visible ? (floorf(radius) + 1.0f) : -1e30f;

    g_P[g] = make_float4(cxp, cyp, r_int, pxv - cxp);
    g_Q[g] = make_float4(pyv - cyp,
                         -0.5f * NL2E * (ce * idet),
                          NL2E * (b * idet),
                         -0.5f * NL2E * (ae * idet));
    g_R[g] = make_float4(opv, col0, col1, col2);
    g_Z[g] = zc;
}

__global__ void __launch_bounds__(256)
rasterize_kernel(float* __restrict__ out) {
    __shared__ float4 sP[NG];    // staged, sorted order
    __shared__ float4 sQ[NG];
    __shared__ float4 sR[NG];
    __shared__ float  sZs[NG];
    __shared__ float  zv[NG];
    __shared__ int    lidx[NG];
    __shared__ int    s_off[16];
    __shared__ int    s_cnt;

    const int tid  = threadIdx.x;
    const int lane = tid & 31, wid = tid >> 5;

    const int t = blockIdx.x;
    const int tile_x0 = (t % NTILES_X) * 16;
    const int tile_y0 = (t / NTILES_X) * 16;
    const float tx0 = (float)tile_x0, tx1 = (float)(tile_x0 + 15);
    const float ty0 = (float)tile_y0, ty1 = (float)(tile_y0 + 15);

    // ---------------- cull (reads g_P from L2) -----------------------------------
    const float4 P0 = g_P[tid];
    const float4 P1 = g_P[tid + 256];
    const bool p0 = (P0.x - P0.z <= tx1) && (P0.x + P0.z >= tx0) &&
                    (P0.y - P0.z <= ty1) && (P0.y + P0.z >= ty0);
    const bool p1 = (P1.x - P1.z <= tx1) && (P1.x + P1.z >= tx0) &&
                    (P1.y - P1.z <= ty1) && (P1.y + P1.z >= ty0);
    const unsigned b0 = __ballot_sync(0xffffffffu, p0);
    const unsigned b1 = __ballot_sync(0xffffffffu, p1);
    if (lane == 0) { s_off[wid] = __popc(b0); s_off[8 + wid] = __popc(b1); }
    __syncthreads();

    if (wid == 0) {
        int v = (lane < 16) ? s_off[lane] : 0;
        int inc = v;
        #pragma unroll
        for (int d = 1; d < 16; d <<= 1) {
            const int n = __shfl_up_sync(0xffffffffu, inc, d);
            if (lane >= d) inc += n;
        }
        if (lane < 16) s_off[lane] = inc - v;
        if (lane == 15) s_cnt = inc;
    }
    __syncthreads();

    if (p0) {
        const int dst = s_off[wid] + __popc(b0 & ((1u << lane) - 1u));
        lidx[dst] = tid;        zv[dst] = g_Z[tid];
    }
    if (p1) {
        const int dst = s_off[8 + wid] + __popc(b1 & ((1u << lane) - 1u));
        lidx[dst] = tid + 256;  zv[dst] = g_Z[tid + 256];
    }
    __syncthreads();
    const int cnt = s_cnt;

    // -------- rank sort (z desc, index asc) + stage sorted gaussians to shared ---
    // lidx is index-ascending so position-asc tie-break == original-index asc
    for (int k = tid; k < cnt; k += 256) {
        const float zk = zv[k];
        int rank = 0;
        for (int j = 0; j < cnt; j++) {
            const float zj = zv[j];
            rank += (zj > zk) || (zj == zk && j < k);
        }
        const int gi = lidx[k];
        sP[rank] = g_P[gi];     // L2-hot
        sQ[rank] = g_Q[gi];
        sR[rank] = g_R[gi];
        sZs[rank] = zk;
    }
    __syncthreads();

    // ---------------- composite (sequential shared reads) ------------------------
    const int px = tile_x0 + (tid & 15);
    const int py = tile_y0 + (tid >> 4);
    const float gx = (float)px, gy = (float)py;

    float Tr = 1.0f, cr = 0.0f, cg = 0.0f, cb = 0.0f, asum = 0.0f;
    int jhit = -1;

    #define BODY(JJ) {                                                        \
        const float4 P = sP[JJ];                                              \
        const bool in = (fabsf(gx - P.x) <= P.z) && (fabsf(gy - P.y) <= P.z); \
        if (__any_sync(0xffffffffu, in)) {                                    \
            const float4 Q = sQ[JJ];                                          \
            const float4 R = sR[JJ];                                          \
            const float dx = (gx - P.x) - P.w;                                \
            const float dy = (gy - P.y) - Q.x;                                \
            const float e  = dx*(Q.y*dx + Q.z*dy) + (Q.w*dy)*dy;              \
            float al = fminf(R.x * ex2(e), 0.99f);                            \
            al = in ? al : 0.0f;                                              \
            const float w = al * Tr;                                          \
            cr += w * R.y; cg += w * R.z; cb += w * R.w; asum += w;           \
            jhit = (jhit < 0 && w > 0.01f) ? (JJ) : jhit;                     \
            Tr = Tr - al * Tr;                                                \
        }                                                                     \
    }

    const int cnt4 = cnt & ~3;
    bool done = false;
    for (int j = 0; j < cnt4; j += 4) {
        BODY(j); BODY(j+1); BODY(j+2); BODY(j+3);
        if (__all_sync(0xffffffffu, Tr < 1e-7f)) { done = true; break; }
    }
    if (!done) {
        for (int j = cnt4; j < cnt; j++) BODY(j);
    }
    #undef BODY

    float depth = 0.0f;
    if (jhit >= 0) depth = sZs[jhit];

    const int pix = py * W + px;
    out[pix*3 + 0] = fminf(fmaxf(cr, 0.0f), 1.0f);
    out[pix*3 + 1] = fminf(fmaxf(cg, 0.0f), 1.0f);
    out[pix*3 + 2] = fminf(fmaxf(cb, 0.0f), 1.0f);
    out[(size_t)H*W*3 + pix] = depth;
    out[(size_t)H*W*4 + pix] = fminf(fmaxf(asum, 0.0f), 1.0f);
}

extern "C" void kernel_launch(void* const* d_in, const int* in_sizes, int n_in,
                              void* d_out, int out_size) {
    const float* means  = (const float*)d_in[0];
    const float* scales = (const float*)d_in[1];
    const float* rots   = (const float*)d_in[2];
    const float* colors = (const float*)d_in[3];
    const float* ops    = (const float*)d_in[4];
    const float* Kc     = (const float*)d_in[5];
    const float* Tm     = (const float*)d_in[6];
    float* out = (float*)d_out;

    preprocess_kernel<<<4, 128>>>(means, scales, rots, colors, ops, Kc, Tm,
                                  out + (size_t)H * W * 5);
    rasterize_kernel<<<300, 256>>>(out);
}